// round 1
// baseline (speedup 1.0000x reference)
#include <cuda_runtime.h>

// Closed-form symmetry constraint:
// For each (batch, class c in {0,1,2}) group of size m with u = x - 0.5:
//   sum_{i<j} (u_i+u_j)^2 = (m-2)*Su2 + Su^2
//   sum_{i<j} (y_i-y_j)^2 = m*Sy2 - Sy^2
//   pairs = m*(m-1)/2
// Output scalar = total / max(count, 1)

__device__ float g_total;
__device__ float g_count;
__device__ unsigned int g_done;

__global__ void __launch_bounds__(256, 8)
sym_moments_kernel(const float* __restrict__ kp,   // [B, N, 2]
                   const int*   __restrict__ cls,  // [B, N]
                   float* __restrict__ out,
                   int N)
{
    const int b = blockIdx.x;
    const float2* kpb = reinterpret_cast<const float2*>(kp) + (size_t)b * N;
    const int*    cb  = cls + (size_t)b * N;

    float su[3]  = {0.f, 0.f, 0.f};
    float su2[3] = {0.f, 0.f, 0.f};
    float sy[3]  = {0.f, 0.f, 0.f};
    float sy2[3] = {0.f, 0.f, 0.f};
    float cnt[3] = {0.f, 0.f, 0.f};

    for (int i = threadIdx.x; i < N; i += blockDim.x) {
        int c = cb[i];
        if ((unsigned)c <= 2u) {
            float2 p = kpb[i];
            float u = p.x - 0.5f;
            su[c]  += u;
            su2[c] += u * u;
            sy[c]  += p.y;
            sy2[c] += p.y * p.y;
            cnt[c] += 1.f;
        }
    }

    // Warp reduction of 15 values
    #pragma unroll
    for (int c = 0; c < 3; c++) {
        #pragma unroll
        for (int off = 16; off > 0; off >>= 1) {
            su[c]  += __shfl_down_sync(0xFFFFFFFFu, su[c],  off);
            su2[c] += __shfl_down_sync(0xFFFFFFFFu, su2[c], off);
            sy[c]  += __shfl_down_sync(0xFFFFFFFFu, sy[c],  off);
            sy2[c] += __shfl_down_sync(0xFFFFFFFFu, sy2[c], off);
            cnt[c] += __shfl_down_sync(0xFFFFFFFFu, cnt[c], off);
        }
    }

    __shared__ float s[8][15];
    const int wid  = threadIdx.x >> 5;
    const int lane = threadIdx.x & 31;
    if (lane == 0) {
        #pragma unroll
        for (int c = 0; c < 3; c++) {
            s[wid][c * 5 + 0] = su[c];
            s[wid][c * 5 + 1] = su2[c];
            s[wid][c * 5 + 2] = sy[c];
            s[wid][c * 5 + 3] = sy2[c];
            s[wid][c * 5 + 4] = cnt[c];
        }
    }
    __syncthreads();

    if (threadIdx.x == 0) {
        float tot = 0.f, count = 0.f;
        #pragma unroll
        for (int c = 0; c < 3; c++) {
            float Su = 0.f, Su2 = 0.f, Sy = 0.f, Sy2 = 0.f, m = 0.f;
            #pragma unroll
            for (int w = 0; w < 8; w++) {
                Su  += s[w][c * 5 + 0];
                Su2 += s[w][c * 5 + 1];
                Sy  += s[w][c * 5 + 2];
                Sy2 += s[w][c * 5 + 3];
                m   += s[w][c * 5 + 4];
            }
            tot   += (m - 2.f) * Su2 + Su * Su + m * Sy2 - Sy * Sy;
            count += 0.5f * m * (m - 1.f);
        }
        atomicAdd(&g_total, tot);
        atomicAdd(&g_count, count);
        __threadfence();
        unsigned int done = atomicAdd(&g_done, 1u);
        if (done == gridDim.x - 1) {
            // Last block: all other blocks' atomics are visible (fenced above).
            float t = *((volatile float*)&g_total);
            float c = *((volatile float*)&g_count);
            out[0] = t / fmaxf(c, 1.f);
            // Reset for the next graph replay (deterministic self-cleaning).
            *((volatile float*)&g_total) = 0.f;
            *((volatile float*)&g_count) = 0.f;
            __threadfence();
            *((volatile unsigned int*)&g_done) = 0u;
        }
    }
}

extern "C" void kernel_launch(void* const* d_in, const int* in_sizes, int n_in,
                              void* d_out, int out_size)
{
    const float* kp  = (const float*)d_in[0];   // [B, N, 2] float32
    const int*   cls = (const int*)d_in[1];     // [B, N] int32
    float* out = (float*)d_out;

    const int BN = in_sizes[1];   // B * N
    const int N  = 512;
    const int B  = BN / N;        // 256

    sym_moments_kernel<<<B, 256>>>(kp, cls, out, N);
}

// round 3
// speedup vs baseline: 1.2043x; 1.2043x over previous
#include <cuda_runtime.h>

// Closed-form symmetry constraint:
// For each (batch, class c in {0,1,2}) group of size m with u = x - 0.5:
//   sum_{i<j} (u_i+u_j)^2 = (m-2)*Su2 + Su^2
//   sum_{i<j} (y_i-y_j)^2 = m*Sy2 - Sy^2
//   pairs = m*(m-1)/2
// Output scalar = total / max(count, 1)
//
// One warp per batch row. All accumulators in registers (class dim unrolled
// with compile-time indices -- NO dynamic array indexing, no local memory).

__device__ float g_total;
__device__ float g_count;
__device__ unsigned int g_done;

__device__ __forceinline__ void accum(int c, float x, float y,
                                      float (&su)[3], float (&su2)[3],
                                      float (&sy)[3], float (&sy2)[3],
                                      float (&cnt)[3])
{
    const float u = x - 0.5f;
    const float uu = u * u;
    const float yy = y * y;
    #pragma unroll
    for (int k = 0; k < 3; k++) {
        const bool m = (c == k);
        su[k]  += m ? u   : 0.f;
        su2[k] += m ? uu  : 0.f;
        sy[k]  += m ? y   : 0.f;
        sy2[k] += m ? yy  : 0.f;
        cnt[k] += m ? 1.f : 0.f;
    }
}

__global__ void __launch_bounds__(32)
sym_warp_kernel(const float* __restrict__ kp,   // [B, N, 2]
                const int*   __restrict__ cls,  // [B, N]
                float* __restrict__ out,
                int N)
{
    const int b    = blockIdx.x;
    const int lane = threadIdx.x;

    const int4*   cb  = reinterpret_cast<const int4*>(cls + (size_t)b * N);
    const float4* kpb = reinterpret_cast<const float4*>(kp + (size_t)b * N * 2);

    float su[3]  = {0.f, 0.f, 0.f};
    float su2[3] = {0.f, 0.f, 0.f};
    float sy[3]  = {0.f, 0.f, 0.f};
    float sy2[3] = {0.f, 0.f, 0.f};
    float cnt[3] = {0.f, 0.f, 0.f};

    // N = 512: 128 int4 chunks per row, 32 lanes -> 4 chunks per lane.
    const int nChunks = N >> 2;  // int4 chunks
    #pragma unroll 4
    for (int ch = lane; ch < nChunks; ch += 32) {
        const int4   c4  = cb[ch];
        const float4 p01 = kpb[ch * 2];      // (x0,y0,x1,y1)
        const float4 p23 = kpb[ch * 2 + 1];  // (x2,y2,x3,y3)
        accum(c4.x, p01.x, p01.y, su, su2, sy, sy2, cnt);
        accum(c4.y, p01.z, p01.w, su, su2, sy, sy2, cnt);
        accum(c4.z, p23.x, p23.y, su, su2, sy, sy2, cnt);
        accum(c4.w, p23.z, p23.w, su, su2, sy, sy2, cnt);
    }

    // Warp-wide butterfly reduction of the 15 register accumulators.
    #pragma unroll
    for (int off = 16; off > 0; off >>= 1) {
        #pragma unroll
        for (int k = 0; k < 3; k++) {
            su[k]  += __shfl_xor_sync(0xFFFFFFFFu, su[k],  off);
            su2[k] += __shfl_xor_sync(0xFFFFFFFFu, su2[k], off);
            sy[k]  += __shfl_xor_sync(0xFFFFFFFFu, sy[k],  off);
            sy2[k] += __shfl_xor_sync(0xFFFFFFFFu, sy2[k], off);
            cnt[k] += __shfl_xor_sync(0xFFFFFFFFu, cnt[k], off);
        }
    }

    if (lane == 0) {
        float tot = 0.f, count = 0.f;
        #pragma unroll
        for (int k = 0; k < 3; k++) {
            const float m = cnt[k];
            tot   += (m - 2.f) * su2[k] + su[k] * su[k] + m * sy2[k] - sy[k] * sy[k];
            count += 0.5f * m * (m - 1.f);
        }
        atomicAdd(&g_total, tot);
        atomicAdd(&g_count, count);
        __threadfence();
        const unsigned int done = atomicAdd(&g_done, 1u);
        if (done == gridDim.x - 1) {
            // Last block: all prior atomics visible (fenced above).
            const float t = *((volatile float*)&g_total);
            const float c = *((volatile float*)&g_count);
            out[0] = t / fmaxf(c, 1.f);
            // Self-reset so each graph replay starts clean (deterministic).
            *((volatile float*)&g_total) = 0.f;
            *((volatile float*)&g_count) = 0.f;
            __threadfence();
            *((volatile unsigned int*)&g_done) = 0u;
        }
    }
}

extern "C" void kernel_launch(void* const* d_in, const int* in_sizes, int n_in,
                              void* d_out, int out_size)
{
    const float* kp  = (const float*)d_in[0];   // [B, N, 2] float32
    const int*   cls = (const int*)d_in[1];     // [B, N] int32
    float* out = (float*)d_out;

    const int BN = in_sizes[1];   // B * N
    const int N  = 512;
    const int B  = BN / N;        // 256

    sym_warp_kernel<<<B, 32>>>(kp, cls, out, N);
}

// round 5
// speedup vs baseline: 1.2444x; 1.0333x over previous
#include <cuda_runtime.h>

// Closed-form symmetry constraint:
// Per (batch, class c in {0,1,2}) group of size m with u = x - 0.5:
//   sum_{i<j} (u_i+u_j)^2 = (m-2)*Su2 + Su^2
//   sum_{i<j} (y_i-y_j)^2 = m*Sy2 - Sy^2
//   pairs = m*(m-1)/2
// Output scalar = total / max(count, 1)
//
// Grid = 32 blocks x 256 threads. Each of the 8 warps per block owns one
// batch row (8 rows/block, 32*8 = 256 rows). All accumulators live in
// registers (class dim unrolled, compile-time indices only). Per-block
// shared combine -> only 3 global atomics per block (96 total) to keep the
// same-address L2 atomic serialization tail short.

__device__ float g_total;
__device__ float g_count;
__device__ unsigned int g_done;

__device__ __forceinline__ void accum(int c, float x, float y,
                                      float (&su)[3], float (&su2)[3],
                                      float (&sy)[3], float (&sy2)[3],
                                      float (&cnt)[3])
{
    const float u = x - 0.5f;
    const float uu = u * u;
    const float yy = y * y;
    #pragma unroll
    for (int k = 0; k < 3; k++) {
        const bool m = (c == k);
        su[k]  += m ? u   : 0.f;
        su2[k] += m ? uu  : 0.f;
        sy[k]  += m ? y   : 0.f;
        sy2[k] += m ? yy  : 0.f;
        cnt[k] += m ? 1.f : 0.f;
    }
}

__global__ void __launch_bounds__(256)
sym_block_kernel(const float* __restrict__ kp,   // [B, N, 2]
                 const int*   __restrict__ cls,  // [B, N]
                 float* __restrict__ out,
                 int N)
{
    const int wid  = threadIdx.x >> 5;     // warp in block = row in group
    const int lane = threadIdx.x & 31;
    const int b    = blockIdx.x * 8 + wid; // batch row for this warp

    const int4*   cb  = reinterpret_cast<const int4*>(cls + (size_t)b * N);
    const float4* kpb = reinterpret_cast<const float4*>(kp + (size_t)b * N * 2);

    float su[3]  = {0.f, 0.f, 0.f};
    float su2[3] = {0.f, 0.f, 0.f};
    float sy[3]  = {0.f, 0.f, 0.f};
    float sy2[3] = {0.f, 0.f, 0.f};
    float cnt[3] = {0.f, 0.f, 0.f};

    // N = 512: 128 int4 chunks per row, 32 lanes -> 4 chunks per lane.
    const int nChunks = N >> 2;
    #pragma unroll 4
    for (int ch = lane; ch < nChunks; ch += 32) {
        const int4   c4  = cb[ch];
        const float4 p01 = kpb[ch * 2];      // (x0,y0,x1,y1)
        const float4 p23 = kpb[ch * 2 + 1];  // (x2,y2,x3,y3)
        accum(c4.x, p01.x, p01.y, su, su2, sy, sy2, cnt);
        accum(c4.y, p01.z, p01.w, su, su2, sy, sy2, cnt);
        accum(c4.z, p23.x, p23.y, su, su2, sy, sy2, cnt);
        accum(c4.w, p23.z, p23.w, su, su2, sy, sy2, cnt);
    }

    // Warp butterfly reduction of the 15 register moments.
    #pragma unroll
    for (int off = 16; off > 0; off >>= 1) {
        #pragma unroll
        for (int k = 0; k < 3; k++) {
            su[k]  += __shfl_xor_sync(0xFFFFFFFFu, su[k],  off);
            su2[k] += __shfl_xor_sync(0xFFFFFFFFu, su2[k], off);
            sy[k]  += __shfl_xor_sync(0xFFFFFFFFu, sy[k],  off);
            sy2[k] += __shfl_xor_sync(0xFFFFFFFFu, sy2[k], off);
            cnt[k] += __shfl_xor_sync(0xFFFFFFFFu, cnt[k], off);
        }
    }

    // Collapse this row's moments to (tot, count); combine 8 warps in shared.
    __shared__ float2 s[8];
    if (lane == 0) {
        float tot = 0.f, count = 0.f;
        #pragma unroll
        for (int k = 0; k < 3; k++) {
            const float m = cnt[k];
            tot   += (m - 2.f) * su2[k] + su[k] * su[k] + m * sy2[k] - sy[k] * sy[k];
            count += 0.5f * m * (m - 1.f);
        }
        s[wid] = make_float2(tot, count);
    }
    __syncthreads();

    if (threadIdx.x == 0) {
        float tot = 0.f, count = 0.f;
        #pragma unroll
        for (int w = 0; w < 8; w++) { tot += s[w].x; count += s[w].y; }

        atomicAdd(&g_total, tot);
        atomicAdd(&g_count, count);
        __threadfence();
        const unsigned int done = atomicAdd(&g_done, 1u);
        if (done == gridDim.x - 1) {
            // Last block: all prior atomics visible (fenced above).
            const float t = *((volatile float*)&g_total);
            const float c = *((volatile float*)&g_count);
            out[0] = t / fmaxf(c, 1.f);
            // Self-reset so each graph replay starts clean (deterministic).
            *((volatile float*)&g_total) = 0.f;
            *((volatile float*)&g_count) = 0.f;
            __threadfence();
            *((volatile unsigned int*)&g_done) = 0u;
        }
    }
}

extern "C" void kernel_launch(void* const* d_in, const int* in_sizes, int n_in,
                              void* d_out, int out_size)
{
    const float* kp  = (const float*)d_in[0];   // [B, N, 2] float32
    const int*   cls = (const int*)d_in[1];     // [B, N] int32
    float* out = (float*)d_out;

    const int BN = in_sizes[1];   // B * N
    const int N  = 512;
    const int B  = BN / N;        // 256
    (void)B;

    sym_block_kernel<<<32, 256>>>(kp, cls, out, N);
}